// round 14
// baseline (speedup 1.0000x reference)
#include <cuda_runtime.h>
#include <cuda_bf16.h>
#include <cstdint>

// ---------------- problem constants ----------------
#define BB   256
#define CC   3
#define HH   224
#define WWD  224
#define RET  32
#define GDIM 9216          // 3 * 3 * 32 * 32
#define HGN  1024
#define HLN  256
#define HOUT 1280          // HG + HL

#define S1   12            // split-K GEMM1: 9216 -> Kc=768 (24 tiles); grid 768
#define S2   8             // split-K out GEMM: 1024 -> Kc=128; grid 640
#define S3   2             // split-K hl GEMM:  256 -> Kc=128

// ---------------- scratch (device globals; no allocation allowed) ----------
__device__ float part1[S1 * BB * HGN];
__device__ float part2[S2 * BB * HOUT];
__device__ float part3[S3 * BB * HOUT];

// bf16 hi/lo operands. A-side: [rows][K]. B-side: natural [K][N].
__device__ __align__(16) __nv_bfloat16 g_h [BB * GDIM],  g_l [BB * GDIM];
__device__ __align__(16) __nv_bfloat16 h1_h[BB * HGN],   h1_l[BB * HGN];
__device__ __align__(16) __nv_bfloat16 h2_h[BB * HLN],   h2_l[BB * HLN];
__device__ __align__(16) __nv_bfloat16 w1_h[GDIM * HGN], w1_l[GDIM * HGN];
__device__ __align__(16) __nv_bfloat16 w3_h[HGN * HOUT], w3_l[HGN * HOUT];
__device__ __align__(16) __nv_bfloat16 w4_h[HLN * HOUT], w4_l[HLN * HOUT];

// ---------------- PTX helpers ----------------------------------------------
__device__ __forceinline__ void cp16(uint32_t smem_dst, const void* gsrc) {
    asm volatile("cp.async.cg.shared.global [%0], [%1], 16;"
                 :: "r"(smem_dst), "l"(gsrc) : "memory");
}
__device__ __forceinline__ void cp_commit() {
    asm volatile("cp.async.commit_group;" ::: "memory");
}
template<int NG>
__device__ __forceinline__ void cp_wait() {
    asm volatile("cp.async.wait_group %0;" :: "n"(NG) : "memory");
}
__device__ __forceinline__ void ldm_x4(uint32_t* r, uint32_t addr) {
    asm volatile("ldmatrix.sync.aligned.m8n8.x4.shared.b16 {%0,%1,%2,%3}, [%4];"
                 : "=r"(r[0]), "=r"(r[1]), "=r"(r[2]), "=r"(r[3]) : "r"(addr));
}
__device__ __forceinline__ void ldm_x4_t(uint32_t* r, uint32_t addr) {
    asm volatile("ldmatrix.sync.aligned.m8n8.x4.trans.shared.b16 {%0,%1,%2,%3}, [%4];"
                 : "=r"(r[0]), "=r"(r[1]), "=r"(r[2]), "=r"(r[3]) : "r"(addr));
}
__device__ __forceinline__ void mma_bf16(float* c, const uint32_t* a, const uint32_t* b) {
    asm volatile("mma.sync.aligned.m16n8k16.row.col.f32.bf16.bf16.f32 "
                 "{%0,%1,%2,%3}, {%4,%5,%6,%7}, {%8,%9}, {%0,%1,%2,%3};"
                 : "+f"(c[0]), "+f"(c[1]), "+f"(c[2]), "+f"(c[3])
                 : "r"(a[0]), "r"(a[1]), "r"(a[2]), "r"(a[3]),
                   "r"(b[0]), "r"(b[1]));
}
// pack two fp32 into bf16x2 hi word + bf16x2 lo-residual word.
// Same RN rounding as before; bf16->fp32 for residual is an exact shift/mask.
__device__ __forceinline__ void split2(float x, float y,
                                       uint32_t& hw, uint32_t& lw) {
    asm("cvt.rn.bf16x2.f32 %0, %1, %2;" : "=r"(hw) : "f"(y), "f"(x));
    float hx = __uint_as_float(hw << 16);
    float hy = __uint_as_float(hw & 0xFFFF0000u);
    asm("cvt.rn.bf16x2.f32 %0, %1, %2;" : "=r"(lw) : "f"(y - hy), "f"(x - hx));
}

// ------- fused W splits: W4 | W1 | W3, 8 elems/thread, one launch ----------
#define W4_C (HLN * HOUT / 8)
#define W1_C (GDIM * HGN / 8)
#define W3_C (HGN * HOUT / 8)
#define CONV_TOT (W4_C + W1_C + W3_C)

__global__ void conv_all_kernel(const float* __restrict__ W1p,
                                const float* __restrict__ W3p,
                                const float* __restrict__ W4p) {
    int i = blockIdx.x * 256 + threadIdx.x;
    if (i >= CONV_TOT) return;
    const float* src;
    __nv_bfloat16 *oh, *ol;
    if (i < W4_C)              { src = W4p; oh = w4_h; ol = w4_l; }
    else if (i < W4_C + W1_C)  { i -= W4_C; src = W1p; oh = w1_h; ol = w1_l; }
    else                       { i -= W4_C + W1_C; src = W3p; oh = w3_h; ol = w3_l; }
    float4 a = ((const float4*)src)[i * 2];
    float4 b = ((const float4*)src)[i * 2 + 1];
    uint4 hq, lq;
    split2(a.x, a.y, hq.x, lq.x);
    split2(a.z, a.w, hq.y, lq.y);
    split2(b.x, b.y, hq.z, lq.z);
    split2(b.z, b.w, hq.w, lq.w);
    ((uint4*)oh)[i] = hq;
    ((uint4*)ol)[i] = lq;
}

// ------- fused foveation (2 px/thread) + location FC -----------------------
#define FOV_BLOCKS (BB * GDIM / 2 / 256)    // 4608
#define LOC_BLOCKS (BB / 2)                 // 128 (2 batches per 256-thr block)

__global__ void fov_loc_kernel(const float* __restrict__ img,
                               const float* __restrict__ loc,
                               const float* __restrict__ W2,
                               const float* __restrict__ b2) {
    if (blockIdx.x >= FOV_BLOCKS) {
        int bb = (blockIdx.x - FOV_BLOCKS) * 2 + (threadIdx.x >> 7);
        int n  = (threadIdx.x & 127) * 2;
        float l0 = loc[bb * 2 + 0];
        float l1 = loc[bb * 2 + 1];
        float v0 = fmaxf(fmaf(l0, W2[n],     fmaf(l1, W2[HLN + n],     b2[n])),     0.0f);
        float v1 = fmaxf(fmaf(l0, W2[n + 1], fmaf(l1, W2[HLN + n + 1], b2[n + 1])), 0.0f);
        uint32_t hw, lw;
        split2(v0, v1, hw, lw);
        ((uint32_t*)h2_h)[(bb * HLN + n) / 2] = hw;
        ((uint32_t*)h2_l)[(bb * HLN + n) / 2] = lw;
        return;
    }
    int idx2 = blockIdx.x * 256 + threadIdx.x;
    int idx = idx2 * 2;
    int b  = idx / GDIM;
    int r  = idx - b * GDIM;
    int z  = r / (CC * RET * RET);
    int r2 = r - z * (CC * RET * RET);
    int c  = r2 / (RET * RET);
    int p  = r2 - c * (RET * RET);
    int y  = p >> 5;
    int x  = p & 31;          // even

    float dr = (loc[b * 2 + 0] + 1.0f) * 0.5f * (float)WWD;
    float dc = (loc[b * 2 + 1] + 1.0f) * 0.5f * (float)WWD;
    int half = 16 << z;
    int top  = (int)(dr - (float)half);
    int left = (int)(dc - (float)half);

    const float* im = img + ((size_t)b * CC + c) * (HH * WWD);
    float v0, v1;
    if (z == 0) {
        const float* p0 = im + (top + y) * WWD + (left + x);
        v0 = p0[0];
        v1 = p0[1];
    } else {
        int off = (z == 2) ? 1 : 0;
        int yy  = top  + (y << z) + off;
        int xx  = left + (x << z) + off;
        int st  = 1 << z;
        const float* p0 = im + yy * WWD + xx;
        v0 = 0.25f * (p0[0] + p0[1] + p0[WWD] + p0[WWD + 1]);
        const float* p1 = p0 + st;
        v1 = 0.25f * (p1[0] + p1[1] + p1[WWD] + p1[WWD + 1]);
    }
    uint32_t hw, lw;
    split2(v0, v1, hw, lw);
    ((uint32_t*)g_h)[idx2] = hw;
    ((uint32_t*)g_l)[idx2] = lw;
}

// ---------------- split-bf16 tensor-core split-K GEMM (proven core) --------
__global__ __launch_bounds__(128, 5)
void mma_gemm_kernel(const __nv_bfloat16* __restrict__ Ah,
                     const __nv_bfloat16* __restrict__ Al,
                     const __nv_bfloat16* __restrict__ Bh,
                     const __nv_bfloat16* __restrict__ Bl,
                     float* __restrict__ part, int M, int N, int K, int Kc) {
    __shared__ __nv_bfloat16 sA[2][2][64][40];   // [stage][h/l][m][k]
    __shared__ __nv_bfloat16 sB[2][2][32][72];   // [stage][h/l][k][n]

    const int tid  = threadIdx.x;
    const int lane = tid & 31;
    const int warp = tid >> 5;
    const int bm   = blockIdx.y;
    const int bn   = blockIdx.x;
    const int sz   = blockIdx.z;
    const int kbase = sz * Kc;
    const int T     = Kc / 32;
    const int wm = (warp & 1) * 32;
    const int wn = (warp >> 1) * 32;

    const uint32_t sa0 = (uint32_t)__cvta_generic_to_shared(&sA[0][0][0][0]);
    const uint32_t sb0 = (uint32_t)__cvta_generic_to_shared(&sB[0][0][0][0]);

    auto load_stage = [&](int it, int s) {
        const int k0 = kbase + it * 32;
        #pragma unroll
        for (int t = 0; t < 4; t++) {
            int hl  = t >> 1;
            int id2 = (t & 1) * 128 + tid;
            int r   = id2 >> 2;
            int c   = (id2 & 3) * 8;
            const __nv_bfloat16* src = (hl ? Al : Ah) + (size_t)(bm * 64 + r) * K + k0 + c;
            cp16(sa0 + (uint32_t)(s * 10240 + hl * 5120 + r * 80 + c * 2), src);
        }
        #pragma unroll
        for (int t = 0; t < 4; t++) {
            int hl  = t >> 1;
            int id2 = (t & 1) * 128 + tid;
            int r   = id2 >> 3;
            int c   = (id2 & 7) * 8;
            const __nv_bfloat16* src = (hl ? Bl : Bh) + (size_t)(k0 + r) * N + bn * 64 + c;
            cp16(sb0 + (uint32_t)(s * 9216 + hl * 4608 + r * 144 + c * 2), src);
        }
        cp_commit();
    };

    float acc[2][4][4] = {};

    const uint32_t a_off = (uint32_t)((wm + (lane & 15)) * 80 + (lane >> 4) * 16);
    const int bm_m = lane >> 3;
    const int bm_j = lane & 7;
    const uint32_t b_row_part = (uint32_t)(((bm_m & 1) * 8 + bm_j) * 144);
    const uint32_t b_col_part = (uint32_t)((wn + (bm_m >> 1) * 8) * 2);

    load_stage(0, 0);
    int buf = 0;
    for (int it = 0; it < T; it++) {
        if (it + 1 < T) { load_stage(it + 1, buf ^ 1); cp_wait<1>(); }
        else            { cp_wait<0>(); }
        __syncthreads();

        const uint32_t sa_s = sa0 + buf * 10240;
        const uint32_t sb_s = sb0 + buf * 9216;

        #pragma unroll
        for (int k16 = 0; k16 < 32; k16 += 16) {
            uint32_t aH[2][4], aL[2][4], bH[4][2], bL[4][2], tmp[4];
            #pragma unroll
            for (int mt = 0; mt < 2; mt++) {
                ldm_x4(aH[mt], sa_s        + a_off + mt * (16 * 80) + k16 * 2);
                ldm_x4(aL[mt], sa_s + 5120 + a_off + mt * (16 * 80) + k16 * 2);
            }
            #pragma unroll
            for (int np = 0; np < 2; np++) {
                uint32_t addr = b_row_part + (uint32_t)(k16 * 144)
                              + b_col_part + (uint32_t)(np * 16 * 2);
                ldm_x4_t(tmp, sb_s + addr);
                bH[np * 2][0] = tmp[0];     bH[np * 2][1] = tmp[1];
                bH[np * 2 + 1][0] = tmp[2]; bH[np * 2 + 1][1] = tmp[3];
                ldm_x4_t(tmp, sb_s + 4608 + addr);
                bL[np * 2][0] = tmp[0];     bL[np * 2][1] = tmp[1];
                bL[np * 2 + 1][0] = tmp[2]; bL[np * 2 + 1][1] = tmp[3];
            }
            #pragma unroll
            for (int mt = 0; mt < 2; mt++)
                #pragma unroll
                for (int nt = 0; nt < 4; nt++) {
                    mma_bf16(acc[mt][nt], aH[mt], bH[nt]);
                    mma_bf16(acc[mt][nt], aL[mt], bH[nt]);
                    mma_bf16(acc[mt][nt], aH[mt], bL[nt]);
                }
        }
        __syncthreads();
        buf ^= 1;
    }

    float* pout = part + (size_t)sz * M * N;
    const int gm  = bm * 64 + wm + (lane >> 2);
    const int gn0 = bn * 64 + wn + (lane & 3) * 2;
    #pragma unroll
    for (int mt = 0; mt < 2; mt++)
        #pragma unroll
        for (int nt = 0; nt < 4; nt++) {
            int row = gm + mt * 16;
            int col = gn0 + nt * 8;
            *(float2*)&pout[(size_t)row * N + col] =
                make_float2(acc[mt][nt][0], acc[mt][nt][1]);
            *(float2*)&pout[(size_t)(row + 8) * N + col] =
                make_float2(acc[mt][nt][2], acc[mt][nt][3]);
        }
}

// ------- reduce 1: h1 = relu(sum_s part1 + b1) -> bf16 hi/lo directly ------
__global__ void reduce1_kernel(const float* __restrict__ b1) {
    int idx4 = blockIdx.x * blockDim.x + threadIdx.x;
    if (idx4 >= BB * HGN / 4) return;
    int idx = idx4 * 4;
    int n   = idx % HGN;
    float4 s = *(const float4*)(part1 + idx);
    #pragma unroll
    for (int z = 1; z < S1; z++) {
        float4 v = *(const float4*)(part1 + (size_t)z * BB * HGN + idx);
        s.x += v.x; s.y += v.y; s.z += v.z; s.w += v.w;
    }
    float4 bv = *(const float4*)(b1 + n);
    s.x = fmaxf(s.x + bv.x, 0.0f);
    s.y = fmaxf(s.y + bv.y, 0.0f);
    s.z = fmaxf(s.z + bv.z, 0.0f);
    s.w = fmaxf(s.w + bv.w, 0.0f);
    uint2 hq, lq;
    split2(s.x, s.y, hq.x, lq.x);
    split2(s.z, s.w, hq.y, lq.y);
    ((uint2*)h1_h)[idx4] = hq;
    ((uint2*)h1_l)[idx4] = lq;
}

// ---------------- final reduce: out = relu(Σpart2+b3) + relu(Σpart3+b4) ----
__global__ void final_reduce_kernel(const float* __restrict__ b3,
                                    const float* __restrict__ b4,
                                    float* __restrict__ out) {
    int idx4 = blockIdx.x * blockDim.x + threadIdx.x;
    if (idx4 >= BB * HOUT / 4) return;
    int idx = idx4 * 4;
    int n   = idx % HOUT;

    float4 sg = *(const float4*)(part2 + idx);
    #pragma unroll
    for (int z = 1; z < S2; z++) {
        float4 v = *(const float4*)(part2 + (size_t)z * BB * HOUT + idx);
        sg.x += v.x; sg.y += v.y; sg.z += v.z; sg.w += v.w;
    }
    float4 sl = *(const float4*)(part3 + idx);
    #pragma unroll
    for (int z = 1; z < S3; z++) {
        float4 v = *(const float4*)(part3 + (size_t)z * BB * HOUT + idx);
        sl.x += v.x; sl.y += v.y; sl.z += v.z; sl.w += v.w;
    }
    float4 g3 = *(const float4*)(b3 + n);
    float4 g4 = *(const float4*)(b4 + n);
    float4 o;
    o.x = fmaxf(sg.x + g3.x, 0.0f) + fmaxf(sl.x + g4.x, 0.0f);
    o.y = fmaxf(sg.y + g3.y, 0.0f) + fmaxf(sl.y + g4.y, 0.0f);
    o.z = fmaxf(sg.z + g3.z, 0.0f) + fmaxf(sl.z + g4.z, 0.0f);
    o.w = fmaxf(sg.w + g3.w, 0.0f) + fmaxf(sl.w + g4.w, 0.0f);
    *(float4*)(out + idx) = o;
}

// ---------------- launch ----------------------------------------------------
extern "C" void kernel_launch(void* const* d_in, const int* in_sizes, int n_in,
                              void* d_out, int out_size) {
    const float* images    = (const float*)d_in[0];
    const float* locations = (const float*)d_in[1];
    const float* W1        = (const float*)d_in[2];
    const float* b1        = (const float*)d_in[3];
    const float* W2        = (const float*)d_in[4];
    const float* b2        = (const float*)d_in[5];
    const float* W3        = (const float*)d_in[6];
    const float* b3        = (const float*)d_in[7];
    const float* W4        = (const float*)d_in[8];
    const float* b4        = (const float*)d_in[9];
    float* out = (float*)d_out;
    (void)in_sizes; (void)n_in; (void)out_size;

    void *p1p, *p2p, *p3p;
    void *ghp, *glp, *h1hp, *h1lp, *h2hp, *h2lp;
    void *w1hp, *w1lp, *w3hp, *w3lp, *w4hp, *w4lp;
    cudaGetSymbolAddress(&p1p,  part1);
    cudaGetSymbolAddress(&p2p,  part2);
    cudaGetSymbolAddress(&p3p,  part3);
    cudaGetSymbolAddress(&ghp,  g_h);  cudaGetSymbolAddress(&glp,  g_l);
    cudaGetSymbolAddress(&h1hp, h1_h); cudaGetSymbolAddress(&h1lp, h1_l);
    cudaGetSymbolAddress(&h2hp, h2_h); cudaGetSymbolAddress(&h2lp, h2_l);
    cudaGetSymbolAddress(&w1hp, w1_h); cudaGetSymbolAddress(&w1lp, w1_l);
    cudaGetSymbolAddress(&w3hp, w3_h); cudaGetSymbolAddress(&w3lp, w3_l);
    cudaGetSymbolAddress(&w4hp, w4_h); cudaGetSymbolAddress(&w4lp, w4_l);

    // 1) all W splits (one launch)
    conv_all_kernel<<<(CONV_TOT + 255) / 256, 256>>>(W1, W3, W4);

    // 2) foveation + location FC (one launch)
    fov_loc_kernel<<<FOV_BLOCKS + LOC_BLOCKS, 256>>>(images, locations, W2, b2);

    // 3) hl partials: h2 @ W4  (M=256, N=1280, K=256, S=2)
    mma_gemm_kernel<<<dim3(HOUT / 64, BB / 64, S3), 128>>>(
        (const __nv_bfloat16*)h2hp, (const __nv_bfloat16*)h2lp,
        (const __nv_bfloat16*)w4hp, (const __nv_bfloat16*)w4lp,
        (float*)p3p, BB, HOUT, HLN, HLN / S3);

    // 4) GEMM1 partials: g @ W1 (M=256, N=1024, K=9216, S=12)  [ncu window]
    mma_gemm_kernel<<<dim3(HGN / 64, BB / 64, S1), 128>>>(
        (const __nv_bfloat16*)ghp, (const __nv_bfloat16*)glp,
        (const __nv_bfloat16*)w1hp, (const __nv_bfloat16*)w1lp,
        (float*)p1p, BB, HGN, GDIM, GDIM / S1);

    // 5) h1 = relu(sum part1 + b1) -> bf16 hi/lo directly
    reduce1_kernel<<<(BB * HGN / 4 + 255) / 256, 256>>>(b1);

    // 6) out partials: h1 @ W3 (M=256, N=1280, K=1024, S=8)
    mma_gemm_kernel<<<dim3(HOUT / 64, BB / 64, S2), 128>>>(
        (const __nv_bfloat16*)h1hp, (const __nv_bfloat16*)h1lp,
        (const __nv_bfloat16*)w3hp, (const __nv_bfloat16*)w3lp,
        (float*)p2p, BB, HOUT, HGN, HGN / S2);

    // 7) out = relu(sum part2 + b3) + relu(sum part3 + b4)
    final_reduce_kernel<<<(BB * HOUT / 4 + 255) / 256, 256>>>(b3, b4, out);
}

// round 15
// speedup vs baseline: 1.1134x; 1.1134x over previous
#include <cuda_runtime.h>
#include <cuda_bf16.h>
#include <cstdint>

// ---------------- problem constants ----------------
#define BB   256
#define CC   3
#define HH   224
#define WWD  224
#define RET  32
#define GDIM 9216          // 3 * 3 * 32 * 32
#define HGN  1024
#define HLN  256
#define HOUT 1280          // HG + HL

#define S1   9             // split-K GEMM1: 9216 -> Kc=1024 (32 tiles)  [R13 cfg]
#define S2   4             // split-K out GEMM: 1024 -> Kc=256           [R13 cfg]
#define S3   2             // split-K hl GEMM:  256 -> Kc=128

// ---------------- scratch (device globals; no allocation allowed) ----------
__device__ float part1[S1 * BB * HGN];
__device__ float part2[S2 * BB * HOUT];
__device__ float part3[S3 * BB * HOUT];

// bf16 hi/lo operands. A-side: [rows][K]. B-side: natural [K][N].
__device__ __align__(16) __nv_bfloat16 g_h [BB * GDIM],  g_l [BB * GDIM];
__device__ __align__(16) __nv_bfloat16 h1_h[BB * HGN],   h1_l[BB * HGN];
__device__ __align__(16) __nv_bfloat16 h2_h[BB * HLN],   h2_l[BB * HLN];
__device__ __align__(16) __nv_bfloat16 w1_h[GDIM * HGN], w1_l[GDIM * HGN];
__device__ __align__(16) __nv_bfloat16 w3_h[HGN * HOUT], w3_l[HGN * HOUT];
__device__ __align__(16) __nv_bfloat16 w4_h[HLN * HOUT], w4_l[HLN * HOUT];

// ---------------- PTX helpers ----------------------------------------------
__device__ __forceinline__ void cp16(uint32_t smem_dst, const void* gsrc) {
    asm volatile("cp.async.cg.shared.global [%0], [%1], 16;"
                 :: "r"(smem_dst), "l"(gsrc) : "memory");
}
__device__ __forceinline__ void cp_commit() {
    asm volatile("cp.async.commit_group;" ::: "memory");
}
template<int NG>
__device__ __forceinline__ void cp_wait() {
    asm volatile("cp.async.wait_group %0;" :: "n"(NG) : "memory");
}
__device__ __forceinline__ void ldm_x4(uint32_t* r, uint32_t addr) {
    asm volatile("ldmatrix.sync.aligned.m8n8.x4.shared.b16 {%0,%1,%2,%3}, [%4];"
                 : "=r"(r[0]), "=r"(r[1]), "=r"(r[2]), "=r"(r[3]) : "r"(addr));
}
__device__ __forceinline__ void ldm_x4_t(uint32_t* r, uint32_t addr) {
    asm volatile("ldmatrix.sync.aligned.m8n8.x4.trans.shared.b16 {%0,%1,%2,%3}, [%4];"
                 : "=r"(r[0]), "=r"(r[1]), "=r"(r[2]), "=r"(r[3]) : "r"(addr));
}
__device__ __forceinline__ void mma_bf16(float* c, const uint32_t* a, const uint32_t* b) {
    asm volatile("mma.sync.aligned.m16n8k16.row.col.f32.bf16.bf16.f32 "
                 "{%0,%1,%2,%3}, {%4,%5,%6,%7}, {%8,%9}, {%0,%1,%2,%3};"
                 : "+f"(c[0]), "+f"(c[1]), "+f"(c[2]), "+f"(c[3])
                 : "r"(a[0]), "r"(a[1]), "r"(a[2]), "r"(a[3]),
                   "r"(b[0]), "r"(b[1]));
}
// pack two fp32 into bf16x2 hi word + bf16x2 lo-residual word (RN, bit-exact
// with the scalar formulation; bf16->fp32 is an exact shift).
__device__ __forceinline__ void split2(float x, float y,
                                       uint32_t& hw, uint32_t& lw) {
    asm("cvt.rn.bf16x2.f32 %0, %1, %2;" : "=r"(hw) : "f"(y), "f"(x));
    float hx = __uint_as_float(hw << 16);
    float hy = __uint_as_float(hw & 0xFFFF0000u);
    asm("cvt.rn.bf16x2.f32 %0, %1, %2;" : "=r"(lw) : "f"(y - hy), "f"(x - hx));
}

// ------- fused prep: W splits + foveation + location FC (ONE launch) -------
// Block ranges: [0, CONV_B) W-split | [CONV_B, +FOV_B) foveate | tail loc FC.
#define W4_C (HLN * HOUT / 8)
#define W1_C (GDIM * HGN / 8)
#define W3_C (HGN * HOUT / 8)
#define CONV_TOT (W4_C + W1_C + W3_C)
#define CONV_B ((CONV_TOT + 255) / 256)     // 5408
#define FOV_B  (BB * GDIM / 2 / 256)        // 4608
#define LOC_B  (BB / 2)                     // 128
#define PREP_B (CONV_B + FOV_B + LOC_B)

__global__ void prep_kernel(const float* __restrict__ img,
                            const float* __restrict__ loc,
                            const float* __restrict__ W1p,
                            const float* __restrict__ W3p,
                            const float* __restrict__ W4p,
                            const float* __restrict__ W2,
                            const float* __restrict__ b2) {
    if (blockIdx.x < CONV_B) {
        // ---- W hi/lo splits, 8 elems/thread ----
        int i = blockIdx.x * 256 + threadIdx.x;
        if (i >= CONV_TOT) return;
        const float* src;
        __nv_bfloat16 *oh, *ol;
        if (i < W4_C)              { src = W4p; oh = w4_h; ol = w4_l; }
        else if (i < W4_C + W1_C)  { i -= W4_C; src = W1p; oh = w1_h; ol = w1_l; }
        else                       { i -= W4_C + W1_C; src = W3p; oh = w3_h; ol = w3_l; }
        float4 a = ((const float4*)src)[i * 2];
        float4 b = ((const float4*)src)[i * 2 + 1];
        uint4 hq, lq;
        split2(a.x, a.y, hq.x, lq.x);
        split2(a.z, a.w, hq.y, lq.y);
        split2(b.x, b.y, hq.z, lq.z);
        split2(b.z, b.w, hq.w, lq.w);
        ((uint4*)oh)[i] = hq;
        ((uint4*)ol)[i] = lq;
        return;
    }
    if (blockIdx.x >= CONV_B + FOV_B) {
        // ---- location FC: 2 batches per block ----
        int bb = (blockIdx.x - CONV_B - FOV_B) * 2 + (threadIdx.x >> 7);
        int n  = (threadIdx.x & 127) * 2;
        float l0 = loc[bb * 2 + 0];
        float l1 = loc[bb * 2 + 1];
        float v0 = fmaxf(fmaf(l0, W2[n],     fmaf(l1, W2[HLN + n],     b2[n])),     0.0f);
        float v1 = fmaxf(fmaf(l0, W2[n + 1], fmaf(l1, W2[HLN + n + 1], b2[n + 1])), 0.0f);
        uint32_t hw, lw;
        split2(v0, v1, hw, lw);
        ((uint32_t*)h2_h)[(bb * HLN + n) / 2] = hw;
        ((uint32_t*)h2_l)[(bb * HLN + n) / 2] = lw;
        return;
    }
    // ---- foveation, 2 px/thread ----
    int idx2 = (blockIdx.x - CONV_B) * 256 + threadIdx.x;
    int idx = idx2 * 2;
    int b  = idx / GDIM;
    int r  = idx - b * GDIM;
    int z  = r / (CC * RET * RET);
    int r2 = r - z * (CC * RET * RET);
    int c  = r2 / (RET * RET);
    int p  = r2 - c * (RET * RET);
    int y  = p >> 5;
    int x  = p & 31;          // even

    float dr = (loc[b * 2 + 0] + 1.0f) * 0.5f * (float)WWD;
    float dc = (loc[b * 2 + 1] + 1.0f) * 0.5f * (float)WWD;
    int half = 16 << z;
    int top  = (int)(dr - (float)half);
    int left = (int)(dc - (float)half);

    const float* im = img + ((size_t)b * CC + c) * (HH * WWD);
    float v0, v1;
    if (z == 0) {
        const float* p0 = im + (top + y) * WWD + (left + x);
        v0 = p0[0];
        v1 = p0[1];
    } else {
        int off = (z == 2) ? 1 : 0;
        int yy  = top  + (y << z) + off;
        int xx  = left + (x << z) + off;
        int st  = 1 << z;
        const float* p0 = im + yy * WWD + xx;
        v0 = 0.25f * (p0[0] + p0[1] + p0[WWD] + p0[WWD + 1]);
        const float* p1 = p0 + st;
        v1 = 0.25f * (p1[0] + p1[1] + p1[WWD] + p1[WWD + 1]);
    }
    uint32_t hw, lw;
    split2(v0, v1, hw, lw);
    ((uint32_t*)g_h)[idx2] = hw;
    ((uint32_t*)g_l)[idx2] = lw;
}

// ---------------- split-bf16 tensor-core split-K GEMM (R13 config) ---------
__global__ __launch_bounds__(128, 4)
void mma_gemm_kernel(const __nv_bfloat16* __restrict__ Ah,
                     const __nv_bfloat16* __restrict__ Al,
                     const __nv_bfloat16* __restrict__ Bh,
                     const __nv_bfloat16* __restrict__ Bl,
                     float* __restrict__ part, int M, int N, int K, int Kc) {
    __shared__ __nv_bfloat16 sA[2][2][64][40];   // [stage][h/l][m][k]
    __shared__ __nv_bfloat16 sB[2][2][32][72];   // [stage][h/l][k][n]

    const int tid  = threadIdx.x;
    const int lane = tid & 31;
    const int warp = tid >> 5;
    const int bm   = blockIdx.y;
    const int bn   = blockIdx.x;
    const int sz   = blockIdx.z;
    const int kbase = sz * Kc;
    const int T     = Kc / 32;
    const int wm = (warp & 1) * 32;
    const int wn = (warp >> 1) * 32;

    const uint32_t sa0 = (uint32_t)__cvta_generic_to_shared(&sA[0][0][0][0]);
    const uint32_t sb0 = (uint32_t)__cvta_generic_to_shared(&sB[0][0][0][0]);

    auto load_stage = [&](int it, int s) {
        const int k0 = kbase + it * 32;
        #pragma unroll
        for (int t = 0; t < 4; t++) {
            int hl  = t >> 1;
            int id2 = (t & 1) * 128 + tid;
            int r   = id2 >> 2;
            int c   = (id2 & 3) * 8;
            const __nv_bfloat16* src = (hl ? Al : Ah) + (size_t)(bm * 64 + r) * K + k0 + c;
            cp16(sa0 + (uint32_t)(s * 10240 + hl * 5120 + r * 80 + c * 2), src);
        }
        #pragma unroll
        for (int t = 0; t < 4; t++) {
            int hl  = t >> 1;
            int id2 = (t & 1) * 128 + tid;
            int r   = id2 >> 3;
            int c   = (id2 & 7) * 8;
            const __nv_bfloat16* src = (hl ? Bl : Bh) + (size_t)(k0 + r) * N + bn * 64 + c;
            cp16(sb0 + (uint32_t)(s * 9216 + hl * 4608 + r * 144 + c * 2), src);
        }
        cp_commit();
    };

    float acc[2][4][4] = {};

    const uint32_t a_off = (uint32_t)((wm + (lane & 15)) * 80 + (lane >> 4) * 16);
    const int bm_m = lane >> 3;
    const int bm_j = lane & 7;
    const uint32_t b_row_part = (uint32_t)(((bm_m & 1) * 8 + bm_j) * 144);
    const uint32_t b_col_part = (uint32_t)((wn + (bm_m >> 1) * 8) * 2);

    load_stage(0, 0);
    int buf = 0;
    for (int it = 0; it < T; it++) {
        if (it + 1 < T) { load_stage(it + 1, buf ^ 1); cp_wait<1>(); }
        else            { cp_wait<0>(); }
        __syncthreads();

        const uint32_t sa_s = sa0 + buf * 10240;
        const uint32_t sb_s = sb0 + buf * 9216;

        #pragma unroll
        for (int k16 = 0; k16 < 32; k16 += 16) {
            uint32_t aH[2][4], aL[2][4], bH[4][2], bL[4][2], tmp[4];
            #pragma unroll
            for (int mt = 0; mt < 2; mt++) {
                ldm_x4(aH[mt], sa_s        + a_off + mt * (16 * 80) + k16 * 2);
                ldm_x4(aL[mt], sa_s + 5120 + a_off + mt * (16 * 80) + k16 * 2);
            }
            #pragma unroll
            for (int np = 0; np < 2; np++) {
                uint32_t addr = b_row_part + (uint32_t)(k16 * 144)
                              + b_col_part + (uint32_t)(np * 16 * 2);
                ldm_x4_t(tmp, sb_s + addr);
                bH[np * 2][0] = tmp[0];     bH[np * 2][1] = tmp[1];
                bH[np * 2 + 1][0] = tmp[2]; bH[np * 2 + 1][1] = tmp[3];
                ldm_x4_t(tmp, sb_s + 4608 + addr);
                bL[np * 2][0] = tmp[0];     bL[np * 2][1] = tmp[1];
                bL[np * 2 + 1][0] = tmp[2]; bL[np * 2 + 1][1] = tmp[3];
            }
            #pragma unroll
            for (int mt = 0; mt < 2; mt++)
                #pragma unroll
                for (int nt = 0; nt < 4; nt++) {
                    mma_bf16(acc[mt][nt], aH[mt], bH[nt]);
                    mma_bf16(acc[mt][nt], aL[mt], bH[nt]);
                    mma_bf16(acc[mt][nt], aH[mt], bL[nt]);
                }
        }
        __syncthreads();
        buf ^= 1;
    }

    float* pout = part + (size_t)sz * M * N;
    const int gm  = bm * 64 + wm + (lane >> 2);
    const int gn0 = bn * 64 + wn + (lane & 3) * 2;
    #pragma unroll
    for (int mt = 0; mt < 2; mt++)
        #pragma unroll
        for (int nt = 0; nt < 4; nt++) {
            int row = gm + mt * 16;
            int col = gn0 + nt * 8;
            *(float2*)&pout[(size_t)row * N + col] =
                make_float2(acc[mt][nt][0], acc[mt][nt][1]);
            *(float2*)&pout[(size_t)(row + 8) * N + col] =
                make_float2(acc[mt][nt][2], acc[mt][nt][3]);
        }
}

// ------- reduce 1: h1 = relu(sum_s part1 + b1) -> bf16 hi/lo directly ------
__global__ void reduce1_kernel(const float* __restrict__ b1) {
    int idx4 = blockIdx.x * blockDim.x + threadIdx.x;
    if (idx4 >= BB * HGN / 4) return;
    int idx = idx4 * 4;
    int n   = idx % HGN;
    float4 s = *(const float4*)(part1 + idx);
    #pragma unroll
    for (int z = 1; z < S1; z++) {
        float4 v = *(const float4*)(part1 + (size_t)z * BB * HGN + idx);
        s.x += v.x; s.y += v.y; s.z += v.z; s.w += v.w;
    }
    float4 bv = *(const float4*)(b1 + n);
    s.x = fmaxf(s.x + bv.x, 0.0f);
    s.y = fmaxf(s.y + bv.y, 0.0f);
    s.z = fmaxf(s.z + bv.z, 0.0f);
    s.w = fmaxf(s.w + bv.w, 0.0f);
    uint2 hq, lq;
    split2(s.x, s.y, hq.x, lq.x);
    split2(s.z, s.w, hq.y, lq.y);
    ((uint2*)h1_h)[idx4] = hq;
    ((uint2*)h1_l)[idx4] = lq;
}

// ---------------- final reduce: out = relu(Σpart2+b3) + relu(Σpart3+b4) ----
__global__ void final_reduce_kernel(const float* __restrict__ b3,
                                    const float* __restrict__ b4,
                                    float* __restrict__ out) {
    int idx4 = blockIdx.x * blockDim.x + threadIdx.x;
    if (idx4 >= BB * HOUT / 4) return;
    int idx = idx4 * 4;
    int n   = idx % HOUT;

    float4 sg = *(const float4*)(part2 + idx);
    #pragma unroll
    for (int z = 1; z < S2; z++) {
        float4 v = *(const float4*)(part2 + (size_t)z * BB * HOUT + idx);
        sg.x += v.x; sg.y += v.y; sg.z += v.z; sg.w += v.w;
    }
    float4 sl = *(const float4*)(part3 + idx);
    #pragma unroll
    for (int z = 1; z < S3; z++) {
        float4 v = *(const float4*)(part3 + (size_t)z * BB * HOUT + idx);
        sl.x += v.x; sl.y += v.y; sl.z += v.z; sl.w += v.w;
    }
    float4 g3 = *(const float4*)(b3 + n);
    float4 g4 = *(const float4*)(b4 + n);
    float4 o;
    o.x = fmaxf(sg.x + g3.x, 0.0f) + fmaxf(sl.x + g4.x, 0.0f);
    o.y = fmaxf(sg.y + g3.y, 0.0f) + fmaxf(sl.y + g4.y, 0.0f);
    o.z = fmaxf(sg.z + g3.z, 0.0f) + fmaxf(sl.z + g4.z, 0.0f);
    o.w = fmaxf(sg.w + g3.w, 0.0f) + fmaxf(sl.w + g4.w, 0.0f);
    *(float4*)(out + idx) = o;
}

// ---------------- launch ----------------------------------------------------
extern "C" void kernel_launch(void* const* d_in, const int* in_sizes, int n_in,
                              void* d_out, int out_size) {
    const float* images    = (const float*)d_in[0];
    const float* locations = (const float*)d_in[1];
    const float* W1        = (const float*)d_in[2];
    const float* b1        = (const float*)d_in[3];
    const float* W2        = (const float*)d_in[4];
    const float* b2        = (const float*)d_in[5];
    const float* W3        = (const float*)d_in[6];
    const float* b3        = (const float*)d_in[7];
    const float* W4        = (const float*)d_in[8];
    const float* b4        = (const float*)d_in[9];
    float* out = (float*)d_out;
    (void)in_sizes; (void)n_in; (void)out_size;

    void *p1p, *p2p, *p3p;
    void *ghp, *glp, *h1hp, *h1lp, *h2hp, *h2lp;
    void *w1hp, *w1lp, *w3hp, *w3lp, *w4hp, *w4lp;
    cudaGetSymbolAddress(&p1p,  part1);
    cudaGetSymbolAddress(&p2p,  part2);
    cudaGetSymbolAddress(&p3p,  part3);
    cudaGetSymbolAddress(&ghp,  g_h);  cudaGetSymbolAddress(&glp,  g_l);
    cudaGetSymbolAddress(&h1hp, h1_h); cudaGetSymbolAddress(&h1lp, h1_l);
    cudaGetSymbolAddress(&h2hp, h2_h); cudaGetSymbolAddress(&h2lp, h2_l);
    cudaGetSymbolAddress(&w1hp, w1_h); cudaGetSymbolAddress(&w1lp, w1_l);
    cudaGetSymbolAddress(&w3hp, w3_h); cudaGetSymbolAddress(&w3lp, w3_l);
    cudaGetSymbolAddress(&w4hp, w4_h); cudaGetSymbolAddress(&w4lp, w4_l);

    // 1) all prep in one launch: W splits + foveation + loc FC
    prep_kernel<<<PREP_B, 256>>>(images, locations, W1, W3, W4, W2, b2);

    // 2) hl partials: h2 @ W4  (M=256, N=1280, K=256, S=2)
    mma_gemm_kernel<<<dim3(HOUT / 64, BB / 64, S3), 128>>>(
        (const __nv_bfloat16*)h2hp, (const __nv_bfloat16*)h2lp,
        (const __nv_bfloat16*)w4hp, (const __nv_bfloat16*)w4lp,
        (float*)p3p, BB, HOUT, HLN, HLN / S3);

    // 3) GEMM1 partials: g @ W1 (M=256, N=1024, K=9216, S=9)
    mma_gemm_kernel<<<dim3(HGN / 64, BB / 64, S1), 128>>>(
        (const __nv_bfloat16*)ghp, (const __nv_bfloat16*)glp,
        (const __nv_bfloat16*)w1hp, (const __nv_bfloat16*)w1lp,
        (float*)p1p, BB, HGN, GDIM, GDIM / S1);

    // 4) h1 = relu(sum part1 + b1) -> bf16 hi/lo directly
    reduce1_kernel<<<(BB * HGN / 4 + 255) / 256, 256>>>(b1);

    // 5) out partials: h1 @ W3 (M=256, N=1280, K=1024, S=4)
    mma_gemm_kernel<<<dim3(HOUT / 64, BB / 64, S2), 128>>>(
        (const __nv_bfloat16*)h1hp, (const __nv_bfloat16*)h1lp,
        (const __nv_bfloat16*)w3hp, (const __nv_bfloat16*)w3lp,
        (float*)p2p, BB, HOUT, HGN, HGN / S2);

    // 6) out = relu(sum part2 + b3) + relu(sum part3 + b4)
    final_reduce_kernel<<<(BB * HOUT / 4 + 255) / 256, 256>>>(b3, b4, out);
}

// round 17
// speedup vs baseline: 1.1473x; 1.0305x over previous
#include <cuda_runtime.h>
#include <cuda_bf16.h>
#include <cstdint>

// ---------------- problem constants ----------------
#define BB   256
#define CC   3
#define HH   224
#define WWD  224
#define RET  32
#define GDIM 9216          // 3 * 3 * 32 * 32
#define HGN  1024
#define HLN  256
#define HOUT 1280          // HG + HL

#define S1   9             // split-K GEMM1: 9216 -> Kc=1024 (32 tiles)
#define S2   4             // split-K out GEMM: 1024 -> Kc=256
#define S3   2             // split-K hl GEMM:  256 -> Kc=128

// ---------------- scratch (device globals; no allocation allowed) ----------
__device__ float part1[S1 * BB * HGN];
__device__ float part2[S2 * BB * HOUT];
__device__ float part3[S3 * BB * HOUT];

// bf16 hi/lo operands. A-side: [rows][K]. B-side: natural [K][N].
__device__ __align__(16) __nv_bfloat16 g_h [BB * GDIM],  g_l [BB * GDIM];
__device__ __align__(16) __nv_bfloat16 h1_h[BB * HGN],   h1_l[BB * HGN];
__device__ __align__(16) __nv_bfloat16 h2_h[BB * HLN],   h2_l[BB * HLN];
__device__ __align__(16) __nv_bfloat16 w1_h[GDIM * HGN], w1_l[GDIM * HGN];
__device__ __align__(16) __nv_bfloat16 w3_h[HGN * HOUT], w3_l[HGN * HOUT];
__device__ __align__(16) __nv_bfloat16 w4_h[HLN * HOUT], w4_l[HLN * HOUT];

// ---------------- PTX helpers ----------------------------------------------
__device__ __forceinline__ void cp16(uint32_t smem_dst, const void* gsrc) {
    asm volatile("cp.async.cg.shared.global [%0], [%1], 16;"
                 :: "r"(smem_dst), "l"(gsrc) : "memory");
}
__device__ __forceinline__ void cp_commit() {
    asm volatile("cp.async.commit_group;" ::: "memory");
}
template<int NG>
__device__ __forceinline__ void cp_wait() {
    asm volatile("cp.async.wait_group %0;" :: "n"(NG) : "memory");
}
__device__ __forceinline__ void ldm_x4(uint32_t* r, uint32_t addr) {
    asm volatile("ldmatrix.sync.aligned.m8n8.x4.shared.b16 {%0,%1,%2,%3}, [%4];"
                 : "=r"(r[0]), "=r"(r[1]), "=r"(r[2]), "=r"(r[3]) : "r"(addr));
}
__device__ __forceinline__ void ldm_x4_t(uint32_t* r, uint32_t addr) {
    asm volatile("ldmatrix.sync.aligned.m8n8.x4.trans.shared.b16 {%0,%1,%2,%3}, [%4];"
                 : "=r"(r[0]), "=r"(r[1]), "=r"(r[2]), "=r"(r[3]) : "r"(addr));
}
__device__ __forceinline__ void mma_bf16(float* c, const uint32_t* a, const uint32_t* b) {
    asm volatile("mma.sync.aligned.m16n8k16.row.col.f32.bf16.bf16.f32 "
                 "{%0,%1,%2,%3}, {%4,%5,%6,%7}, {%8,%9}, {%0,%1,%2,%3};"
                 : "+f"(c[0]), "+f"(c[1]), "+f"(c[2]), "+f"(c[3])
                 : "r"(a[0]), "r"(a[1]), "r"(a[2]), "r"(a[3]),
                   "r"(b[0]), "r"(b[1]));
}
// pack two fp32 into bf16x2 hi word + bf16x2 lo-residual word (RN, bit-exact).
__device__ __forceinline__ void split2(float x, float y,
                                       uint32_t& hw, uint32_t& lw) {
    asm("cvt.rn.bf16x2.f32 %0, %1, %2;" : "=r"(hw) : "f"(y), "f"(x));
    float hx = __uint_as_float(hw << 16);
    float hy = __uint_as_float(hw & 0xFFFF0000u);
    asm("cvt.rn.bf16x2.f32 %0, %1, %2;" : "=r"(lw) : "f"(y - hy), "f"(x - hx));
}

// ------- fused prep: W splits + foveation + location FC (ONE launch) -------
#define W4_C (HLN * HOUT / 8)
#define W1_C (GDIM * HGN / 8)
#define W3_C (HGN * HOUT / 8)
#define CONV_TOT (W4_C + W1_C + W3_C)
#define CONV_B ((CONV_TOT + 255) / 256)     // 5408
#define FOV_B  (BB * GDIM / 2 / 256)        // 4608
#define LOC_B  (BB / 2)                     // 128
#define PREP_B (CONV_B + FOV_B + LOC_B)

__global__ void prep_kernel(const float* __restrict__ img,
                            const float* __restrict__ loc,
                            const float* __restrict__ W1p,
                            const float* __restrict__ W3p,
                            const float* __restrict__ W4p,
                            const float* __restrict__ W2,
                            const float* __restrict__ b2) {
    if (blockIdx.x < CONV_B) {
        int i = blockIdx.x * 256 + threadIdx.x;
        if (i >= CONV_TOT) return;
        const float* src;
        __nv_bfloat16 *oh, *ol;
        if (i < W4_C)              { src = W4p; oh = w4_h; ol = w4_l; }
        else if (i < W4_C + W1_C)  { i -= W4_C; src = W1p; oh = w1_h; ol = w1_l; }
        else                       { i -= W4_C + W1_C; src = W3p; oh = w3_h; ol = w3_l; }
        float4 a = ((const float4*)src)[i * 2];
        float4 b = ((const float4*)src)[i * 2 + 1];
        uint4 hq, lq;
        split2(a.x, a.y, hq.x, lq.x);
        split2(a.z, a.w, hq.y, lq.y);
        split2(b.x, b.y, hq.z, lq.z);
        split2(b.z, b.w, hq.w, lq.w);
        ((uint4*)oh)[i] = hq;
        ((uint4*)ol)[i] = lq;
        return;
    }
    if (blockIdx.x >= CONV_B + FOV_B) {
        int bb = (blockIdx.x - CONV_B - FOV_B) * 2 + (threadIdx.x >> 7);
        int n  = (threadIdx.x & 127) * 2;
        float l0 = loc[bb * 2 + 0];
        float l1 = loc[bb * 2 + 1];
        float v0 = fmaxf(fmaf(l0, W2[n],     fmaf(l1, W2[HLN + n],     b2[n])),     0.0f);
        float v1 = fmaxf(fmaf(l0, W2[n + 1], fmaf(l1, W2[HLN + n + 1], b2[n + 1])), 0.0f);
        uint32_t hw, lw;
        split2(v0, v1, hw, lw);
        ((uint32_t*)h2_h)[(bb * HLN + n) / 2] = hw;
        ((uint32_t*)h2_l)[(bb * HLN + n) / 2] = lw;
        return;
    }
    int idx2 = (blockIdx.x - CONV_B) * 256 + threadIdx.x;
    int idx = idx2 * 2;
    int b  = idx / GDIM;
    int r  = idx - b * GDIM;
    int z  = r / (CC * RET * RET);
    int r2 = r - z * (CC * RET * RET);
    int c  = r2 / (RET * RET);
    int p  = r2 - c * (RET * RET);
    int y  = p >> 5;
    int x  = p & 31;          // even

    float dr = (loc[b * 2 + 0] + 1.0f) * 0.5f * (float)WWD;
    float dc = (loc[b * 2 + 1] + 1.0f) * 0.5f * (float)WWD;
    int half = 16 << z;
    int top  = (int)(dr - (float)half);
    int left = (int)(dc - (float)half);

    const float* im = img + ((size_t)b * CC + c) * (HH * WWD);
    float v0, v1;
    if (z == 0) {
        const float* p0 = im + (top + y) * WWD + (left + x);
        v0 = p0[0];
        v1 = p0[1];
    } else {
        int off = (z == 2) ? 1 : 0;
        int yy  = top  + (y << z) + off;
        int xx  = left + (x << z) + off;
        int st  = 1 << z;
        const float* p0 = im + yy * WWD + xx;
        v0 = 0.25f * (p0[0] + p0[1] + p0[WWD] + p0[WWD + 1]);
        const float* p1 = p0 + st;
        v1 = 0.25f * (p1[0] + p1[1] + p1[WWD] + p1[WWD + 1]);
    }
    uint32_t hw, lw;
    split2(v0, v1, hw, lw);
    ((uint32_t*)g_h)[idx2] = hw;
    ((uint32_t*)g_l)[idx2] = lw;
}

// ---------------- split-bf16 tensor-core GEMM body -------------------------
// Pass-major MMA order (HH x8, LH x8, HL x8): per-acc addition order is
// unchanged (HH -> LH -> HL) so results are bit-identical; RAW distance 1 -> 8.
__device__ __forceinline__ void gemm_body(
    const __nv_bfloat16* Ah, const __nv_bfloat16* Al,
    const __nv_bfloat16* Bh, const __nv_bfloat16* Bl,
    float* part, int M, int N, int K, int Kc,
    int bn, int bm, int sz,
    __nv_bfloat16 (*sA)[2][64][40], __nv_bfloat16 (*sB)[2][32][72]) {

    const int tid  = threadIdx.x;
    const int lane = tid & 31;
    const int warp = tid >> 5;
    const int kbase = sz * Kc;
    const int T     = Kc / 32;
    const int wm = (warp & 1) * 32;
    const int wn = (warp >> 1) * 32;

    const uint32_t sa0 = (uint32_t)__cvta_generic_to_shared(&sA[0][0][0][0]);
    const uint32_t sb0 = (uint32_t)__cvta_generic_to_shared(&sB[0][0][0][0]);

    auto load_stage = [&](int it, int s) {
        const int k0 = kbase + it * 32;
        #pragma unroll
        for (int t = 0; t < 4; t++) {
            int hl  = t >> 1;
            int id2 = (t & 1) * 128 + tid;
            int r   = id2 >> 2;
            int c   = (id2 & 3) * 8;
            const __nv_bfloat16* src = (hl ? Al : Ah) + (size_t)(bm * 64 + r) * K + k0 + c;
            cp16(sa0 + (uint32_t)(s * 10240 + hl * 5120 + r * 80 + c * 2), src);
        }
        #pragma unroll
        for (int t = 0; t < 4; t++) {
            int hl  = t >> 1;
            int id2 = (t & 1) * 128 + tid;
            int r   = id2 >> 3;
            int c   = (id2 & 7) * 8;
            const __nv_bfloat16* src = (hl ? Bl : Bh) + (size_t)(k0 + r) * N + bn * 64 + c;
            cp16(sb0 + (uint32_t)(s * 9216 + hl * 4608 + r * 144 + c * 2), src);
        }
        cp_commit();
    };

    float acc[2][4][4] = {};

    const uint32_t a_off = (uint32_t)((wm + (lane & 15)) * 80 + (lane >> 4) * 16);
    const int bm_m = lane >> 3;
    const int bm_j = lane & 7;
    const uint32_t b_row_part = (uint32_t)(((bm_m & 1) * 8 + bm_j) * 144);
    const uint32_t b_col_part = (uint32_t)((wn + (bm_m >> 1) * 8) * 2);

    load_stage(0, 0);
    int buf = 0;
    for (int it = 0; it < T; it++) {
        if (it + 1 < T) { load_stage(it + 1, buf ^ 1); cp_wait<1>(); }
        else            { cp_wait<0>(); }
        __syncthreads();

        const uint32_t sa_s = sa0 + buf * 10240;
        const uint32_t sb_s = sb0 + buf * 9216;

        #pragma unroll
        for (int k16 = 0; k16 < 32; k16 += 16) {
            uint32_t aH[2][4], aL[2][4], bH[4][2], bL[4][2], tmp[4];
            #pragma unroll
            for (int mt = 0; mt < 2; mt++) {
                ldm_x4(aH[mt], sa_s        + a_off + mt * (16 * 80) + k16 * 2);
                ldm_x4(aL[mt], sa_s + 5120 + a_off + mt * (16 * 80) + k16 * 2);
            }
            #pragma unroll
            for (int np = 0; np < 2; np++) {
                uint32_t addr = b_row_part + (uint32_t)(k16 * 144)
                              + b_col_part + (uint32_t)(np * 16 * 2);
                ldm_x4_t(tmp, sb_s + addr);
                bH[np * 2][0] = tmp[0];     bH[np * 2][1] = tmp[1];
                bH[np * 2 + 1][0] = tmp[2]; bH[np * 2 + 1][1] = tmp[3];
                ldm_x4_t(tmp, sb_s + 4608 + addr);
                bL[np * 2][0] = tmp[0];     bL[np * 2][1] = tmp[1];
                bL[np * 2 + 1][0] = tmp[2]; bL[np * 2 + 1][1] = tmp[3];
            }
            // pass-major: 8 independent MMAs per pass
            #pragma unroll
            for (int mt = 0; mt < 2; mt++)
                #pragma unroll
                for (int nt = 0; nt < 4; nt++)
                    mma_bf16(acc[mt][nt], aH[mt], bH[nt]);
            #pragma unroll
            for (int mt = 0; mt < 2; mt++)
                #pragma unroll
                for (int nt = 0; nt < 4; nt++)
                    mma_bf16(acc[mt][nt], aL[mt], bH[nt]);
            #pragma unroll
            for (int mt = 0; mt < 2; mt++)
                #pragma unroll
                for (int nt = 0; nt < 4; nt++)
                    mma_bf16(acc[mt][nt], aH[mt], bL[nt]);
        }
        __syncthreads();
        buf ^= 1;
    }

    float* pout = part + (size_t)sz * M * N;
    const int gm  = bm * 64 + wm + (lane >> 2);
    const int gn0 = bn * 64 + wn + (lane & 3) * 2;
    #pragma unroll
    for (int mt = 0; mt < 2; mt++)
        #pragma unroll
        for (int nt = 0; nt < 4; nt++) {
            int row = gm + mt * 16;
            int col = gn0 + nt * 8;
            *(float2*)&pout[(size_t)row * N + col] =
                make_float2(acc[mt][nt][0], acc[mt][nt][1]);
            *(float2*)&pout[(size_t)(row + 8) * N + col] =
                make_float2(acc[mt][nt][2], acc[mt][nt][3]);
        }
}

// ---- merged launch: z < S1 -> GEMM1 (g @ W1), z >= S1 -> hl (h2 @ W4) -----
__global__ __launch_bounds__(128, 4)
void gemm_merged_kernel() {
    __shared__ __nv_bfloat16 sA[2][2][64][40];
    __shared__ __nv_bfloat16 sB[2][2][32][72];
    if (blockIdx.z < S1) {
        if (blockIdx.x >= HGN / 64) return;    // uniform per-block exit
        gemm_body(g_h, g_l, w1_h, w1_l, part1,
                  BB, HGN, GDIM, GDIM / S1,
                  blockIdx.x, blockIdx.y, blockIdx.z, sA, sB);
    } else {
        gemm_body(h2_h, h2_l, w4_h, w4_l, part3,
                  BB, HOUT, HLN, HLN / S3,
                  blockIdx.x, blockIdx.y, blockIdx.z - S1, sA, sB);
    }
}

// ---- out-GEMM: h1 @ W3 -----------------------------------------------------
__global__ __launch_bounds__(128, 4)
void gemm_out_kernel() {
    __shared__ __nv_bfloat16 sA[2][2][64][40];
    __shared__ __nv_bfloat16 sB[2][2][32][72];
    gemm_body(h1_h, h1_l, w3_h, w3_l, part2,
              BB, HOUT, HGN, HGN / S2,
              blockIdx.x, blockIdx.y, blockIdx.z, sA, sB);
}

// ------- reduce 1: h1 = relu(sum_s part1 + b1) -> bf16 hi/lo directly ------
__global__ void reduce1_kernel(const float* __restrict__ b1) {
    int idx4 = blockIdx.x * blockDim.x + threadIdx.x;
    if (idx4 >= BB * HGN / 4) return;
    int idx = idx4 * 4;
    int n   = idx % HGN;
    float4 s = *(const float4*)(part1 + idx);
    #pragma unroll
    for (int z = 1; z < S1; z++) {
        float4 v = *(const float4*)(part1 + (size_t)z * BB * HGN + idx);
        s.x += v.x; s.y += v.y; s.z += v.z; s.w += v.w;
    }
    float4 bv = *(const float4*)(b1 + n);
    s.x = fmaxf(s.x + bv.x, 0.0f);
    s.y = fmaxf(s.y + bv.y, 0.0f);
    s.z = fmaxf(s.z + bv.z, 0.0f);
    s.w = fmaxf(s.w + bv.w, 0.0f);
    uint2 hq, lq;
    split2(s.x, s.y, hq.x, lq.x);
    split2(s.z, s.w, hq.y, lq.y);
    ((uint2*)h1_h)[idx4] = hq;
    ((uint2*)h1_l)[idx4] = lq;
}

// ---------------- final reduce: out = relu(Σpart2+b3) + relu(Σpart3+b4) ----
__global__ void final_reduce_kernel(const float* __restrict__ b3,
                                    const float* __restrict__ b4,
                                    float* __restrict__ out) {
    int idx4 = blockIdx.x * blockDim.x + threadIdx.x;
    if (idx4 >= BB * HOUT / 4) return;
    int idx = idx4 * 4;
    int n   = idx % HOUT;

    float4 sg = *(const float4*)(part2 + idx);
    #pragma unroll
    for (int z = 1; z < S2; z++) {
        float4 v = *(const float4*)(part2 + (size_t)z * BB * HOUT + idx);
        sg.x += v.x; sg.y += v.y; sg.z += v.z; sg.w += v.w;
    }
    float4 sl = *(const float4*)(part3 + idx);
    #pragma unroll
    for (int z = 1; z < S3; z++) {
        float4 v = *(const float4*)(part3 + (size_t)z * BB * HOUT + idx);
        sl.x += v.x; sl.y += v.y; sl.z += v.z; sl.w += v.w;
    }
    float4 g3 = *(const float4*)(b3 + n);
    float4 g4 = *(const float4*)(b4 + n);
    float4 o;
    o.x = fmaxf(sg.x + g3.x, 0.0f) + fmaxf(sl.x + g4.x, 0.0f);
    o.y = fmaxf(sg.y + g3.y, 0.0f) + fmaxf(sl.y + g4.y, 0.0f);
    o.z = fmaxf(sg.z + g3.z, 0.0f) + fmaxf(sl.z + g4.z, 0.0f);
    o.w = fmaxf(sg.w + g3.w, 0.0f) + fmaxf(sl.w + g4.w, 0.0f);
    *(float4*)(out + idx) = o;
}

// ---------------- launch ----------------------------------------------------
extern "C" void kernel_launch(void* const* d_in, const int* in_sizes, int n_in,
                              void* d_out, int out_size) {
    const float* images    = (const float*)d_in[0];
    const float* locations = (const float*)d_in[1];
    const float* W1        = (const float*)d_in[2];
    const float* b1        = (const float*)d_in[3];
    const float* W2        = (const float*)d_in[4];
    const float* b2        = (const float*)d_in[5];
    const float* W3        = (const float*)d_in[6];
    const float* b3        = (const float*)d_in[7];
    const float* W4        = (const float*)d_in[8];
    const float* b4        = (const float*)d_in[9];
    float* out = (float*)d_out;
    (void)in_sizes; (void)n_in; (void)out_size;

    // 1) all prep in one launch: W splits + foveation + loc FC
    prep_kernel<<<PREP_B, 256>>>(images, locations, W1, W3, W4, W2, b2);

    // 2) merged GEMM launch: GEMM1 (z<S1) + hl GEMM (z>=S1)
    gemm_merged_kernel<<<dim3(HOUT / 64, BB / 64, S1 + S3), 128>>>();

    // 3) h1 = relu(sum part1 + b1) -> bf16 hi/lo  (512 x 128 for latency)
    reduce1_kernel<<<512, 128>>>(b1);

    // 4) out partials: h1 @ W3 (M=256, N=1280, K=1024, S=4)
    gemm_out_kernel<<<dim3(HOUT / 64, BB / 64, S2), 128>>>();

    // 5) out = relu(sum part2 + b3) + relu(sum part3 + b4)
    final_reduce_kernel<<<(BB * HOUT / 4 + 255) / 256, 256>>>(b3, b4, out);
}